// round 5
// baseline (speedup 1.0000x reference)
#include <cuda_runtime.h>
#include <cstddef>
#include <cstdint>

#define NP 4
#define NS 4
#define NC 64
#define NF 64
#define NB 64
// PS = 16, PSC = 1024, per-psc KQ block = F*C*F = 262144 floats

__device__ float g_weights[NP * NS * NC * NC];           // softmax(scores), 256 KB
__device__ float g_V[NB * NP * NS * NC * NF];            // V = X @ Wv^T, 16 MB

// packed fp32x2 FMA: {d.lo,d.hi} += {a.lo*b.lo, a.hi*b.hi} — exact fp32, 2x rate
__device__ __forceinline__ void ffma2(unsigned long long& acc,
                                      unsigned long long a,
                                      unsigned long long b) {
    asm("fma.rn.f32x2 %0, %1, %2, %0;" : "+l"(acc) : "l"(a), "l"(b));
}

// ---------------------------------------------------------------------------
// Combined kernel: 2048 blocks x 1024 threads, roles interleaved by bid&1.
// EVEN blocks (psc = bid>>1): KQ reduction (DRAM-roofline) + fused softmax.
// ODD  blocks (bp  = bid>>1): V[bp] = X[bp] @ Wv^T, rides in the idle issue
//   slots of the DRAM-bound reduce blocks.
// ---------------------------------------------------------------------------
__global__ void __launch_bounds__(1024, 2)
reduce_softmax_v_kernel(const float* __restrict__ kq,
                        const float* __restrict__ x,
                        const float* __restrict__ wv) {
    __shared__ float sh[NC * (NF + 1) + NC * (NF + 4)];  // 34 KB union

    const int bid = blockIdx.x;
    const int t   = threadIdx.x;

    if ((bid & 1) == 0) {
        // ---- role A: KQ reduction + softmax ----
        const int psc = bid >> 1;
        const int d   = t >> 4;
        const int j   = t & 15;

        const float4* base =
            reinterpret_cast<const float4*>(kq + (size_t)psc * (NF * NC * NF))
            + (d * (NF / 4) + j);

        float4 acc = make_float4(0.f, 0.f, 0.f, 0.f);
#pragma unroll 4
        for (int f = 0; f < NF; ++f) {
            float4 v = __ldcs(base + f * (NC * NF / 4));
            acc.x += v.x; acc.y += v.y; acc.z += v.z; acc.w += v.w;
        }
        float s = (acc.x + acc.y) + (acc.z + acc.w);

        s += __shfl_xor_sync(0xffffffffu, s, 8);
        s += __shfl_xor_sync(0xffffffffu, s, 4);
        s += __shfl_xor_sync(0xffffffffu, s, 2);
        s += __shfl_xor_sync(0xffffffffu, s, 1);

        if (j == 0) sh[d] = s;
        __syncthreads();

        if (t < 32) {
            const float a = sh[t];
            const float b = sh[t + 32];
            float m = fmaxf(a, b);
#pragma unroll
            for (int off = 16; off > 0; off >>= 1)
                m = fmaxf(m, __shfl_xor_sync(0xffffffffu, m, off));
            const float ea = __expf(a - m);
            const float eb = __expf(b - m);
            float ssum = ea + eb;
#pragma unroll
            for (int off = 16; off > 0; off >>= 1)
                ssum += __shfl_xor_sync(0xffffffffu, ssum, off);
            const float inv = 1.0f / ssum;
            g_weights[psc * NC + t]      = ea * inv;
            g_weights[psc * NC + t + 32] = eb * inv;
        }
    } else {
        // ---- role B: V = X @ Wv^T for one (b,ps), float4-vectorized ----
        const int bp = bid >> 1;                    // = b*16 + ps
        float* bufX  = sh;                          // [64][65] : X[c][k]
        float* bufWT = sh + NC * (NF + 1);          // [64][68] : Wv^T[k][f]

        const float* xsrc = x + (size_t)bp * (NC * NF);
#pragma unroll
        for (int r = 0; r < 4; ++r) {
            const int idx = t + r * 1024;
            const int hi  = idx >> 6, lo = idx & 63;
            bufX[hi * (NF + 1) + lo]  = xsrc[idx];
            bufWT[lo * (NF + 4) + hi] = wv[idx];    // wv[f][k] -> bufWT[k][f]
        }
        __syncthreads();

        const int c  = t >> 4;
        const int fq = t & 15;
        float4 acc = make_float4(0.f, 0.f, 0.f, 0.f);
#pragma unroll 8
        for (int k = 0; k < NF; ++k) {
            const float  xk = bufX[c * (NF + 1) + k];
            const float4 w4 = *reinterpret_cast<const float4*>(
                                  &bufWT[k * (NF + 4) + 4 * fq]);
            acc.x += xk * w4.x; acc.y += xk * w4.y;
            acc.z += xk * w4.z; acc.w += xk * w4.w;
        }

        float4* vdst = reinterpret_cast<float4*>(g_V + (size_t)bp * (NC * NF));
        vdst[c * (NF / 4) + fq] = acc;
    }
}

// ---------------------------------------------------------------------------
// Kernel 2: out[b,ps][c][f] = sum_d w[ps][c][d] * V[b,ps][d][f]
// 1024 blocks x 256 threads, fp32x2 packed FMA (FFMA2).
//
// w is staged DUPLICATED in smem: bufWdup[c][2d]=bufWdup[c][2d+1]=w[c][d],
// so {w,w} 64-bit pairs come straight from LDS.128 (no per-iter pack ops).
// Thread (tc,tf): 4 c-rows (tc+16i) x f-slice [4tf,4tf+4).
// Per d4 chunk: 8 w LDS.128 (broadcast: 2 distinct c/warp) + 4 V LDS.128
// + 32 FFMA2  (was 8 LDS + 64 FFMA) -> issue count 0.61x, fma-pipe 0.5x.
// ---------------------------------------------------------------------------
#define WDUP_STRIDE 132  // 2*NF + 4 pad, 16B-aligned rows, bank-spread

__global__ void __launch_bounds__(256)
attn_out_kernel(float* __restrict__ out) {
    __shared__ float bufV[NC * NF];             // V[d][f] flat
    __shared__ float bufWdup[NC * WDUP_STRIDE]; // duplicated w

    const int blk = blockIdx.x;
    const int b   = blk >> 4;
    const int ps  = blk & 15;
    const int t   = threadIdx.x;
    const int tc  = t >> 4;
    const int tf  = t & 15;

    const float4* vsrc = reinterpret_cast<const float4*>(g_V + (size_t)blk * (NC * NF));
    const float4* wsrc = reinterpret_cast<const float4*>(g_weights + (size_t)ps * (NC * NC));
    float4* bv4 = reinterpret_cast<float4*>(bufV);
#pragma unroll
    for (int r = 0; r < 4; ++r) {
        const int i4 = t + r * 256;                  // 0..1023 float4s
        bv4[i4] = vsrc[i4];
        const float4 w  = wsrc[i4];                  // w[c][4d0..4d0+3], c=i4>>4
        const int   c   = i4 >> 4;
        const int   d0  = (i4 & 15) * 4;
        float* dst = &bufWdup[c * WDUP_STRIDE + 2 * d0];
        *reinterpret_cast<float4*>(dst)     = make_float4(w.x, w.x, w.y, w.y);
        *reinterpret_cast<float4*>(dst + 4) = make_float4(w.z, w.z, w.w, w.w);
    }
    __syncthreads();

    unsigned long long o01[4], o23[4];   // {f,f+1} and {f+2,f+3} packed pairs
#pragma unroll
    for (int i = 0; i < 4; ++i) { o01[i] = 0ull; o23[i] = 0ull; }

    const int frow = 4 * tf;

#pragma unroll 4
    for (int d4 = 0; d4 < NC / 4; ++d4) {
        // duplicated w pairs for d = 4d4..4d4+3, all 4 c-rows
        ulonglong2 wA[4], wB[4];   // wA = {{w0,w0},{w1,w1}}, wB = {{w2,w2},{w3,w3}}
#pragma unroll
        for (int i = 0; i < 4; ++i) {
            const ulonglong2* wp = reinterpret_cast<const ulonglong2*>(
                &bufWdup[(tc + 16 * i) * WDUP_STRIDE + 8 * d4]);
            wA[i] = wp[0];
            wB[i] = wp[1];
        }
#pragma unroll
        for (int dd = 0; dd < 4; ++dd) {
            const ulonglong2 v = *reinterpret_cast<const ulonglong2*>(
                &bufV[(4 * d4 + dd) * NF + frow]);   // {f,f+1},{f+2,f+3}
#pragma unroll
            for (int i = 0; i < 4; ++i) {
                const unsigned long long wpair =
                    (dd == 0) ? wA[i].x : (dd == 1) ? wA[i].y
                  : (dd == 2) ? wB[i].x :             wB[i].y;
                ffma2(o01[i], wpair, v.x);
                ffma2(o23[i], wpair, v.y);
            }
        }
    }

    // out layout: (C, B, P*S*F); out[c, b, ps*F + f], f-slice [4tf,4tf+4)
#pragma unroll
    for (int i = 0; i < 4; ++i) {
        const int c = tc + 16 * i;
        float* orow = out + ((size_t)c * NB + b) * (NP * NS * NF) + (size_t)ps * NF;
        float4 o;
        o.x = __uint_as_float((unsigned)(o01[i] & 0xffffffffull));
        o.y = __uint_as_float((unsigned)(o01[i] >> 32));
        o.z = __uint_as_float((unsigned)(o23[i] & 0xffffffffull));
        o.w = __uint_as_float((unsigned)(o23[i] >> 32));
        *reinterpret_cast<float4*>(&orow[frow]) = o;
    }
}

// ---------------------------------------------------------------------------
extern "C" void kernel_launch(void* const* d_in, const int* in_sizes, int n_in,
                              void* d_out, int out_size) {
    const float* X  = (const float*)d_in[0];  // (B, P*S*C*F)
    const float* KQ = (const float*)d_in[1];  // (P,S,C,F,C,F) — 1 GB
    const float* Wv = (const float*)d_in[2];  // (F, F)
    float* out = (float*)d_out;               // (C, B, P*S*F)

    reduce_softmax_v_kernel<<<2048, 1024>>>(KQ, X, Wv);
    attn_out_kernel<<<NB * NP * NS, 256>>>(out);
}

// round 6
// speedup vs baseline: 1.0261x; 1.0261x over previous
#include <cuda_runtime.h>
#include <cstddef>
#include <cstdint>

#define NP 4
#define NS 4
#define NC 64
#define NF 64
#define NB 64
// PS = 16, PSC = 1024, per-psc KQ block = F*C*F = 262144 floats

__device__ float g_weights[NP * NS * NC * NC];           // softmax(scores), 256 KB
__device__ float g_V[NB * NP * NS * NC * NF];            // V = X @ Wv^T, 16 MB

// packed fp32x2 FMA: {d.lo,d.hi} += {a.lo*b.lo, a.hi*b.hi} — exact fp32, 2x rate
__device__ __forceinline__ void ffma2(unsigned long long& acc,
                                      unsigned long long a,
                                      unsigned long long b) {
    asm("fma.rn.f32x2 %0, %1, %2, %0;" : "+l"(acc) : "l"(a), "l"(b));
}
// pack one fp32 into both lanes of a 64-bit pair (ALU pipe, 1 instr)
__device__ __forceinline__ unsigned long long dup2(float w) {
    unsigned long long r;
    asm("mov.b64 %0, {%1, %1};" : "=l"(r) : "f"(w));
    return r;
}

// ---------------------------------------------------------------------------
// Combined kernel: 2048 blocks x 1024 threads, roles interleaved by bid&1.
// EVEN blocks (psc = bid>>1): KQ reduction (DRAM-roofline) + fused softmax.
// ODD  blocks (bp  = bid>>1): V[bp] = X[bp] @ Wv^T, rides in the idle issue
//   slots of the DRAM-bound reduce blocks.  (unchanged — at 89.5% of HBM spec)
// ---------------------------------------------------------------------------
__global__ void __launch_bounds__(1024, 2)
reduce_softmax_v_kernel(const float* __restrict__ kq,
                        const float* __restrict__ x,
                        const float* __restrict__ wv) {
    __shared__ float sh[NC * (NF + 1) + NC * (NF + 4)];  // 34 KB union

    const int bid = blockIdx.x;
    const int t   = threadIdx.x;

    if ((bid & 1) == 0) {
        // ---- role A: KQ reduction + softmax ----
        const int psc = bid >> 1;
        const int d   = t >> 4;
        const int j   = t & 15;

        const float4* base =
            reinterpret_cast<const float4*>(kq + (size_t)psc * (NF * NC * NF))
            + (d * (NF / 4) + j);

        float4 acc = make_float4(0.f, 0.f, 0.f, 0.f);
#pragma unroll 4
        for (int f = 0; f < NF; ++f) {
            float4 v = __ldcs(base + f * (NC * NF / 4));
            acc.x += v.x; acc.y += v.y; acc.z += v.z; acc.w += v.w;
        }
        float s = (acc.x + acc.y) + (acc.z + acc.w);

        s += __shfl_xor_sync(0xffffffffu, s, 8);
        s += __shfl_xor_sync(0xffffffffu, s, 4);
        s += __shfl_xor_sync(0xffffffffu, s, 2);
        s += __shfl_xor_sync(0xffffffffu, s, 1);

        if (j == 0) sh[d] = s;
        __syncthreads();

        if (t < 32) {
            const float a = sh[t];
            const float b = sh[t + 32];
            float m = fmaxf(a, b);
#pragma unroll
            for (int off = 16; off > 0; off >>= 1)
                m = fmaxf(m, __shfl_xor_sync(0xffffffffu, m, off));
            const float ea = __expf(a - m);
            const float eb = __expf(b - m);
            float ssum = ea + eb;
#pragma unroll
            for (int off = 16; off > 0; off >>= 1)
                ssum += __shfl_xor_sync(0xffffffffu, ssum, off);
            const float inv = 1.0f / ssum;
            g_weights[psc * NC + t]      = ea * inv;
            g_weights[psc * NC + t + 32] = eb * inv;
        }
    } else {
        // ---- role B: V = X @ Wv^T for one (b,ps), float4-vectorized ----
        const int bp = bid >> 1;                    // = b*16 + ps
        float* bufX  = sh;                          // [64][65] : X[c][k]
        float* bufWT = sh + NC * (NF + 1);          // [64][68] : Wv^T[k][f]

        const float* xsrc = x + (size_t)bp * (NC * NF);
#pragma unroll
        for (int r = 0; r < 4; ++r) {
            const int idx = t + r * 1024;
            const int hi  = idx >> 6, lo = idx & 63;
            bufX[hi * (NF + 1) + lo]  = xsrc[idx];
            bufWT[lo * (NF + 4) + hi] = wv[idx];    // wv[f][k] -> bufWT[k][f]
        }
        __syncthreads();

        const int c  = t >> 4;
        const int fq = t & 15;
        float4 acc = make_float4(0.f, 0.f, 0.f, 0.f);
#pragma unroll 8
        for (int k = 0; k < NF; ++k) {
            const float  xk = bufX[c * (NF + 1) + k];
            const float4 w4 = *reinterpret_cast<const float4*>(
                                  &bufWT[k * (NF + 4) + 4 * fq]);
            acc.x += xk * w4.x; acc.y += xk * w4.y;
            acc.z += xk * w4.z; acc.w += xk * w4.w;
        }

        float4* vdst = reinterpret_cast<float4*>(g_V + (size_t)bp * (NC * NF));
        vdst[c * (NF / 4) + fq] = acc;
    }
}

// ---------------------------------------------------------------------------
// Kernel 2: out[b,ps][c][f] = sum_d w[ps][c][d] * V[b,ps][d][f]
// 1024 blocks x 256 threads.
// EXACT R3 memory pattern (w reads broadcast, V reads conflict-free float4,
// smem 34 KB) — but the inner product runs on fp32x2 packed FMA with the
// {w,w} pair built in REGISTERS (mov.b64 on the idle ALU pipe), not in smem.
// Per d4 chunk: 8 LDS.128 + 16 MOV64 + 32 FFMA2  (R3: 8 LDS.128 + 64 FFMA).
// ---------------------------------------------------------------------------
__global__ void __launch_bounds__(256)
attn_out_kernel(float* __restrict__ out) {
    __shared__ float bufV[NC * NF];         // V[d][f], flat, rows contiguous
    __shared__ float bufW[NC * (NF + 4)];   // w[c][d], stride 68 (16B-aligned)

    const int blk = blockIdx.x;
    const int b   = blk >> 4;
    const int ps  = blk & 15;
    const int t   = threadIdx.x;
    const int tc  = t >> 4;
    const int tf  = t & 15;

    const float4* vsrc = reinterpret_cast<const float4*>(g_V + (size_t)blk * (NC * NF));
    const float4* wsrc = reinterpret_cast<const float4*>(g_weights + (size_t)ps * (NC * NC));
    float4* bv4 = reinterpret_cast<float4*>(bufV);
#pragma unroll
    for (int r = 0; r < 4; ++r) {
        const int i4 = t + r * 256;                  // 0..1023 float4s
        bv4[i4] = vsrc[i4];
        reinterpret_cast<float4*>(&bufW[(i4 >> 4) * (NF + 4)])[i4 & 15] = wsrc[i4];
    }
    __syncthreads();

    unsigned long long o01[4], o23[4];   // {f,f+1} and {f+2,f+3} packed pairs
#pragma unroll
    for (int i = 0; i < 4; ++i) { o01[i] = 0ull; o23[i] = 0ull; }

    const int frow = 4 * tf;

#pragma unroll 4
    for (int d4 = 0; d4 < NC / 4; ++d4) {
        // V rows for d = 4*d4 .. 4*d4+3, f-slice [frow, frow+4) as u64 pairs
        const ulonglong2 v0 = *reinterpret_cast<const ulonglong2*>(&bufV[(4 * d4 + 0) * NF + frow]);
        const ulonglong2 v1 = *reinterpret_cast<const ulonglong2*>(&bufV[(4 * d4 + 1) * NF + frow]);
        const ulonglong2 v2 = *reinterpret_cast<const ulonglong2*>(&bufV[(4 * d4 + 2) * NF + frow]);
        const ulonglong2 v3 = *reinterpret_cast<const ulonglong2*>(&bufV[(4 * d4 + 3) * NF + frow]);

#pragma unroll
        for (int i = 0; i < 4; ++i) {
            // broadcast LDS.128: only 2 distinct addresses per warp
            const float4 w4 = *reinterpret_cast<const float4*>(
                                  &bufW[(tc + 16 * i) * (NF + 4) + 4 * d4]);
            const unsigned long long wx = dup2(w4.x);
            const unsigned long long wy = dup2(w4.y);
            const unsigned long long wz = dup2(w4.z);
            const unsigned long long ww = dup2(w4.w);
            ffma2(o01[i], wx, v0.x);  ffma2(o23[i], wx, v0.y);
            ffma2(o01[i], wy, v1.x);  ffma2(o23[i], wy, v1.y);
            ffma2(o01[i], wz, v2.x);  ffma2(o23[i], wz, v2.y);
            ffma2(o01[i], ww, v3.x);  ffma2(o23[i], ww, v3.y);
        }
    }

    // out layout: (C, B, P*S*F); out[c, b, ps*F + f], f-slice [frow, frow+4)
#pragma unroll
    for (int i = 0; i < 4; ++i) {
        const int c = tc + 16 * i;
        float* orow = out + ((size_t)c * NB + b) * (NP * NS * NF) + (size_t)ps * NF;
        float4 o;
        o.x = __uint_as_float((unsigned)(o01[i] & 0xffffffffull));
        o.y = __uint_as_float((unsigned)(o01[i] >> 32));
        o.z = __uint_as_float((unsigned)(o23[i] & 0xffffffffull));
        o.w = __uint_as_float((unsigned)(o23[i] >> 32));
        *reinterpret_cast<float4*>(&orow[frow]) = o;
    }
}

// ---------------------------------------------------------------------------
extern "C" void kernel_launch(void* const* d_in, const int* in_sizes, int n_in,
                              void* d_out, int out_size) {
    const float* X  = (const float*)d_in[0];  // (B, P*S*C*F)
    const float* KQ = (const float*)d_in[1];  // (P,S,C,F,C,F) — 1 GB
    const float* Wv = (const float*)d_in[2];  // (F, F)
    float* out = (float*)d_out;               // (C, B, P*S*F)

    reduce_softmax_v_kernel<<<2048, 1024>>>(KQ, X, Wv);
    attn_out_kernel<<<NB * NP * NS, 256>>>(out);
}